// round 4
// baseline (speedup 1.0000x reference)
#include <cuda_runtime.h>
#include <cuda_bf16.h>

#define BATCH  16
#define SEQ    2048
#define DIM    64
#define NCHUNK 8
#define NBLK   (BATCH * NCHUNK)   // 128 blocks: one wave on 148 SMs (barrier-safe)
#define NT     512

// Partial K^T*Q products: [batch][chunk][64][64]. Plain-overwritten every
// replay (no zeroing needed), 2MB -> L2-resident.
__device__ float M_part[BATCH * NCHUNK * DIM * DIM];

// Grid barrier state. bar_gen is monotonically increasing across graph
// replays (never reset -> deterministic, replay-safe).
__device__ unsigned bar_cnt = 0;
__device__ volatile unsigned bar_gen = 0;

typedef unsigned long long u64;

__device__ __forceinline__ u64 pk2(float lo, float hi) {
    u64 r;
    asm("mov.b64 %0, {%1,%2};" : "=l"(r) : "f"(lo), "f"(hi));
    return r;
}
__device__ __forceinline__ void upk2(u64 v, float &lo, float &hi) {
    asm("mov.b64 {%0,%1}, %2;" : "=f"(lo), "=f"(hi) : "l"(v));
}
// packed dual-FMA: d.lo += a.lo*b.lo ; d.hi += a.hi*b.hi
__device__ __forceinline__ void fma2(u64 &d, u64 a, u64 b) {
    asm("fma.rn.f32x2 %0, %1, %2, %0;" : "+l"(d) : "l"(a), "l"(b));
}

__device__ __forceinline__ void grid_barrier() {
    __threadfence();
    __syncthreads();
    if (threadIdx.x == 0) {
        unsigned gen = bar_gen;
        unsigned arrived = atomicAdd(&bar_cnt, 1);
        if (arrived == gridDim.x - 1) {
            bar_cnt = 0;
            __threadfence();
            bar_gen = gen + 1;
        } else {
            while (bar_gen == gen) { }
        }
    }
    __syncthreads();
    __threadfence();
}

// ---------------------------------------------------------------------------
// One persistent kernel: 128 blocks x 512 threads, 41KB static smem.
//  Phase A: 4 groups of 128 threads; group g computes the full 64x64
//           K^T*Q tile over its 64 s-rows (8x4 per-thread tiles, 16 fma2
//           per s-step, K duplicated via register movs -> fma-pipe bound).
//           Group partials tree-reduced through smem, written to M_part.
//  Phase C: O = V @ (sum_c M_part[b][c]) in 2 dim-passes; each thread owns
//           1 V row x 32 output cols; M rows are warp-broadcast LDS.
// ---------------------------------------------------------------------------
__global__ __launch_bounds__(NT, 1)
void fused_attn_kernel(const float* __restrict__ Q,
                       const float* __restrict__ K,
                       const float* __restrict__ V,
                       float* __restrict__ O) {
    // smem regions (union):
    //  Phase A:   Ksh f[64][64] @0 (16KB), Qsh f[64][64] @16K (16KB)
    //  Reduction: Rbuf0 @0 (16KB), Rbuf1 @16K (16KB)
    //  Phase C:   Msh f[32][64] @0 (8KB),  Vsh f[256][33] @8K (33.8KB)
    __shared__ __align__(16) unsigned char smem_raw[8192 + 33792];
    float* Ksh   = (float*)smem_raw;
    float* Qsh   = (float*)(smem_raw + 16384);
    float* Rbuf0 = (float*)smem_raw;
    float* Rbuf1 = (float*)(smem_raw + 16384);
    float* Msh   = (float*)smem_raw;
    float* Vsh   = (float*)(smem_raw + 8192);

    const int blk = blockIdx.x;
    const int t   = threadIdx.x;
    const int b   = blk >> 3;      // batch
    const int c   = blk & 7;       // 256-row s-chunk

    const float* Kc = K + ((size_t)b * SEQ + (size_t)c * 256) * DIM;
    const float* Qc = Q + ((size_t)b * SEQ + (size_t)c * 256) * DIM;

    // ======================= Phase A: partial K^T Q ========================
    const int g  = t >> 7;         // s-group 0..3 (rows g*64 .. g*64+63)
    const int tg = t & 127;
    const int ti = tg >> 4;        // 0..7  -> M rows 8ti..8ti+7
    const int tj = tg & 15;        // 0..15 -> M cols 4tj..4tj+3

    // acc[i][p]: row 8ti+i, col-pair {4tj+2p, 4tj+2p+1}
    u64 acc[8][2];
#pragma unroll
    for (int i = 0; i < 8; i++) { acc[i][0] = 0ull; acc[i][1] = 0ull; }

    for (int sub = 0; sub < 4; sub++) {
        __syncthreads();
        // Stage 16 s-rows per group (64 rows total) of K and Q.
        // Buffer row rb = grp*16 + s  <->  chunk row grp*64 + sub*16 + s.
#pragma unroll
        for (int i = 0; i < 2; i++) {
            int f   = t + NT * i;        // 0..1023
            int rb  = f >> 4;
            int c4  = (f & 15) * 4;
            int grp = rb >> 4;
            int ss  = rb & 15;
            size_t grow = (size_t)(grp * 64 + sub * 16 + ss) * DIM + c4;
            *(float4*)&Ksh[rb * 64 + c4] = *(const float4*)&Kc[grow];
            *(float4*)&Qsh[rb * 64 + c4] = *(const float4*)&Qc[grow];
        }
        __syncthreads();

#pragma unroll
        for (int s = 0; s < 16; s++) {
            const int rb = g * 16 + s;
            float4 k0 = *(const float4*)&Ksh[rb * 64 + 8 * ti];
            float4 k1 = *(const float4*)&Ksh[rb * 64 + 8 * ti + 4];
            ulonglong2 qp = *(const ulonglong2*)&Qsh[rb * 64 + 4 * tj];
            u64 kd;
            kd = pk2(k0.x, k0.x); fma2(acc[0][0], kd, qp.x); fma2(acc[0][1], kd, qp.y);
            kd = pk2(k0.y, k0.y); fma2(acc[1][0], kd, qp.x); fma2(acc[1][1], kd, qp.y);
            kd = pk2(k0.z, k0.z); fma2(acc[2][0], kd, qp.x); fma2(acc[2][1], kd, qp.y);
            kd = pk2(k0.w, k0.w); fma2(acc[3][0], kd, qp.x); fma2(acc[3][1], kd, qp.y);
            kd = pk2(k1.x, k1.x); fma2(acc[4][0], kd, qp.x); fma2(acc[4][1], kd, qp.y);
            kd = pk2(k1.y, k1.y); fma2(acc[5][0], kd, qp.x); fma2(acc[5][1], kd, qp.y);
            kd = pk2(k1.z, k1.z); fma2(acc[6][0], kd, qp.x); fma2(acc[6][1], kd, qp.y);
            kd = pk2(k1.w, k1.w); fma2(acc[7][0], kd, qp.x); fma2(acc[7][1], kd, qp.y);
        }
    }

    // ---- Reduce the 4 group partials: (2,3)->(0,1), then 1->0 ------------
    __syncthreads();
    if (g >= 2) {
        u64* dst = (u64*)((g == 2) ? Rbuf0 : Rbuf1) + (size_t)tg * 16;
#pragma unroll
        for (int i = 0; i < 8; i++) { dst[2 * i] = acc[i][0]; dst[2 * i + 1] = acc[i][1]; }
    }
    __syncthreads();
    if (g < 2) {
        const u64* src = (const u64*)((g == 0) ? Rbuf0 : Rbuf1) + (size_t)tg * 16;
#pragma unroll
        for (int i = 0; i < 8; i++) {
#pragma unroll
            for (int p = 0; p < 2; p++) {
                float a0, a1, p0, p1;
                upk2(acc[i][p], a0, a1);
                upk2(src[2 * i + p], p0, p1);
                acc[i][p] = pk2(a0 + p0, a1 + p1);
            }
        }
    }
    __syncthreads();
    if (g == 1) {
        u64* dst = (u64*)Rbuf0 + (size_t)tg * 16;
#pragma unroll
        for (int i = 0; i < 8; i++) { dst[2 * i] = acc[i][0]; dst[2 * i + 1] = acc[i][1]; }
    }
    __syncthreads();
    if (g == 0) {
        const u64* src = (const u64*)Rbuf0 + (size_t)tg * 16;
        float* mp = M_part + (size_t)blk * DIM * DIM;
#pragma unroll
        for (int i = 0; i < 8; i++) {
            float a0, a1, a2, a3, p0, p1, p2, p3;
            upk2(acc[i][0], a0, a1); upk2(src[2 * i],     p0, p1);
            upk2(acc[i][1], a2, a3); upk2(src[2 * i + 1], p2, p3);
            float4 o; o.x = a0 + p0; o.y = a1 + p1; o.z = a2 + p2; o.w = a3 + p3;
            *(float4*)&mp[(ti * 8 + i) * DIM + 4 * tj] = o;
        }
    }
    __syncthreads();   // Rbuf reads done before Vsh staging overwrites

    // ===== Stage V (dims 0..31) BEFORE the barrier to hide barrier wait ====
    const float* Vc = V + ((size_t)b * SEQ + (size_t)c * 256) * DIM;
#pragma unroll
    for (int i = 0; i < 4; i++) {
        int f   = t + NT * i;      // 0..2047
        int row = f >> 3;
        int c4  = (f & 7) * 4;
        float4 v4 = *(const float4*)&Vc[(size_t)row * DIM + c4];
        Vsh[row * 33 + c4 + 0] = v4.x;
        Vsh[row * 33 + c4 + 1] = v4.y;
        Vsh[row * 33 + c4 + 2] = v4.z;
        Vsh[row * 33 + c4 + 3] = v4.w;
    }

    grid_barrier();    // all M_part partials now visible

    // ============== Phase C: O = V @ (sum of partials), 2 passes ===========
    const int r  = t & 255;       // V row within chunk
    const int ch = t >> 8;        // col half: cols ch*32..ch*32+31

    u64 acc2[16];
#pragma unroll
    for (int p = 0; p < 16; p++) acc2[p] = 0ull;

    const float* Mpb = M_part + (size_t)(b * NCHUNK) * DIM * DIM;

    for (int pass = 0; pass < 2; pass++) {
        if (pass == 1) {
            __syncthreads();   // done reading pass-0 Msh/Vsh
#pragma unroll
            for (int i = 0; i < 4; i++) {
                int f   = t + NT * i;
                int row = f >> 3;
                int c4  = (f & 7) * 4;
                float4 v4 = *(const float4*)&Vc[(size_t)row * DIM + 32 + c4];
                Vsh[row * 33 + c4 + 0] = v4.x;
                Vsh[row * 33 + c4 + 1] = v4.y;
                Vsh[row * 33 + c4 + 2] = v4.z;
                Vsh[row * 33 + c4 + 3] = v4.w;
            }
        }
        // Stage Msh (dims pass*32..pass*32+31): sum 8 L2-resident partials.
        {
            int row = t >> 4;            // 0..31
            int c4  = (t & 15) * 4;
            const float* src = Mpb + (size_t)(pass * 32 + row) * DIM + c4;
            float4 s = *(const float4*)src;
#pragma unroll
            for (int k = 1; k < NCHUNK; k++) {
                float4 v = *(const float4*)(src + (size_t)k * DIM * DIM);
                s.x += v.x; s.y += v.y; s.z += v.z; s.w += v.w;
            }
            *(float4*)&Msh[row * DIM + c4] = s;
        }
        __syncthreads();

#pragma unroll 4
        for (int dp = 0; dp < 32; dp++) {
            float vv = Vsh[r * 33 + dp];
            u64 v2 = pk2(vv, vv);
            const ulonglong2* mr = (const ulonglong2*)&Msh[dp * DIM + ch * 32];
#pragma unroll
            for (int p = 0; p < 8; p++) {
                ulonglong2 m2 = mr[p];
                fma2(acc2[2 * p + 0], v2, m2.x);
                fma2(acc2[2 * p + 1], v2, m2.y);
            }
        }
    }

    // ============================ Write O ==================================
    float* Ob = O + ((size_t)b * SEQ + (size_t)c * 256) * DIM + ch * 32;
#pragma unroll
    for (int p = 0; p < 8; p++) {
        float4 o;
        upk2(acc2[2 * p + 0], o.x, o.y);
        upk2(acc2[2 * p + 1], o.z, o.w);
        *(float4*)(Ob + (size_t)r * DIM + 4 * p) = o;
    }
}

// ---------------------------------------------------------------------------
extern "C" void kernel_launch(void* const* d_in, const int* in_sizes, int n_in,
                              void* d_out, int out_size) {
    const float* Q = (const float*)d_in[0];
    const float* K = (const float*)d_in[1];
    const float* V = (const float*)d_in[2];
    float* O = (float*)d_out;

    fused_attn_kernel<<<NBLK, NT>>>(Q, K, V, O);
}

// round 7
// speedup vs baseline: 1.2323x; 1.2323x over previous
#include <cuda_runtime.h>
#include <cuda_bf16.h>
#include <cstdint>

#define BATCH 16
#define SEQ   2048
#define DIM   64
#define NBLK  128          // 16 batches x 8 seq-chunks; one wave on 148 SMs
#define NT    256

// P[i][j] = M[j][i] partials per (batch,chunk): 64x64 fp32. 2MB, L2-resident.
// Plain-overwritten every replay (no zeroing needed).
__device__ float M_part[NBLK * DIM * DIM];
__device__ unsigned bar_cnt = 0;
__device__ volatile unsigned bar_gen = 0;

#define WA 36   // phase-A row stride in words (64 bf16 data + pad) -> frag banks 4g+tg
#define WV 20   // phase-C V row stride in words (32 bf16 data + pad)

__device__ __forceinline__ uint32_t bf16x2_of(float fo, float fe){
    uint32_t r;
    asm("cvt.rn.bf16x2.f32 %0, %1, %2;" : "=r"(r) : "f"(fo), "f"(fe));
    return r;
}
// split fp32 pair (fe = element at even k, fo = odd k) into hi/lo bf16x2 words
__device__ __forceinline__ void split2(float fe, float fo, uint32_t &hi, uint32_t &lo){
    __nv_bfloat16 he = __float2bfloat16(fe);
    __nv_bfloat16 ho = __float2bfloat16(fo);
    hi = ((uint32_t)__bfloat16_as_ushort(ho) << 16) | (uint32_t)__bfloat16_as_ushort(he);
    lo = bf16x2_of(fo - __bfloat162float(ho), fe - __bfloat162float(he));
}

// m16n8k16 row.col bf16 HMMA, fp32 accumulate in place.
__device__ __forceinline__ void mma16816(float* c, uint32_t a0, uint32_t a1,
                                         uint32_t a2, uint32_t a3,
                                         uint32_t b0, uint32_t b1){
    asm("mma.sync.aligned.m16n8k16.row.col.f32.bf16.bf16.f32 "
        "{%0,%1,%2,%3}, {%4,%5,%6,%7}, {%8,%9}, {%0,%1,%2,%3};"
        : "+f"(c[0]), "+f"(c[1]), "+f"(c[2]), "+f"(c[3])
        : "r"(a0), "r"(a1), "r"(a2), "r"(a3), "r"(b0), "r"(b1));
}

__device__ __forceinline__ void grid_barrier(){
    __threadfence();
    __syncthreads();
    if (threadIdx.x == 0) {
        unsigned gen = bar_gen;
        unsigned arrived = atomicAdd(&bar_cnt, 1);
        if (arrived == gridDim.x - 1) {
            bar_cnt = 0;
            __threadfence();
            bar_gen = gen + 1;
        } else {
            while (bar_gen == gen) { }
        }
    }
    __syncthreads();
    __threadfence();
}

// ---------------------------------------------------------------------------
// Persistent kernel: 128 blocks x 256 threads (8 warps), 38.9KB static smem.
// Phase A: per block (b,c): M-tile over its 256 s-rows via HMMA bf16 split,
//          KT/QT staged transposed [d][s]; C-frags -> P[d2][d1] in M_part.
// grid barrier
// Phase C: O rows = V @ M using MT = P[d][dp] (8 partials summed on the fly),
//          2 v-tiles x 2 dp-passes, HMMA bf16 split.
// ---------------------------------------------------------------------------
__global__ __launch_bounds__(NT, 1)
void fused_attn_hmma(const float* __restrict__ Q, const float* __restrict__ K,
                     const float* __restrict__ V, float* __restrict__ O)
{
    // word layout (union):
    //  Phase A: KThi @0, KTlo @2304, QThi @4608, QTlo @6912   (64 x WA each)
    //  Phase C: MThi @0, MTlo @2304, Vhi @4608, Vlo @7168     (MT 64xWA, V 128xWV)
    __shared__ __align__(16) uint32_t sw[9728];
    uint32_t* KThi = sw;          uint32_t* KTlo = sw + 2304;
    uint32_t* QThi = sw + 4608;   uint32_t* QTlo = sw + 6912;
    uint32_t* MThi = sw;          uint32_t* MTlo = sw + 2304;
    uint32_t* Vhi  = sw + 4608;   uint32_t* Vlo  = sw + 7168;

    const int t = threadIdx.x, warp = t >> 5, lane = t & 31;
    const int g = lane >> 2, tg = lane & 3;        // mma fragment ids
    const int dd = lane & 7, wq = lane >> 3;       // staging ids (wq 0..3)
    const int blk = blockIdx.x, b = blk >> 3, c = blk & 7;

    // ========================== Phase A ====================================
    {
        const int wm = warp & 3, wn = warp >> 2;   // warp tile: m0=wm*16, n0=wn*32
        const int m0 = wm * 16, n0 = wn * 32;
        const float* Kc = K + ((size_t)b * SEQ + (size_t)c * 256) * DIM;
        const float* Qc = Q + ((size_t)b * SEQ + (size_t)c * 256) * DIM;

        float acc[4][4];
#pragma unroll
        for (int nt = 0; nt < 4; nt++)
#pragma unroll
            for (int i = 0; i < 4; i++) acc[nt][i] = 0.0f;

        for (int sub = 0; sub < 4; sub++) {
            __syncthreads();              // prior frag loads done before restage
            const float* Ks = Kc + (size_t)(sub * 64) * DIM;
            const float* Qs = Qc + (size_t)(sub * 64) * DIM;
            const int d = warp * 8 + dd;
#pragma unroll
            for (int j = 0; j < 8; j++) {
                int sp = wq + 4 * j;                     // s-pair 0..31
                float ke = Ks[(size_t)(2 * sp) * DIM + d];
                float ko = Ks[(size_t)(2 * sp + 1) * DIM + d];
                uint32_t hi, lo;
                split2(ke, ko, hi, lo);
                KThi[d * WA + sp] = hi;  KTlo[d * WA + sp] = lo;
                float qe = Qs[(size_t)(2 * sp) * DIM + d];
                float qo = Qs[(size_t)(2 * sp + 1) * DIM + d];
                split2(qe, qo, hi, lo);
                QThi[d * WA + sp] = hi;  QTlo[d * WA + sp] = lo;
            }
            __syncthreads();

#pragma unroll
            for (int ks = 0; ks < 4; ks++) {
                const int kb = ks * 8 + tg;
                uint32_t ah0 = KThi[(m0 + g) * WA + kb];
                uint32_t ah1 = KThi[(m0 + g + 8) * WA + kb];
                uint32_t ah2 = KThi[(m0 + g) * WA + kb + 4];
                uint32_t ah3 = KThi[(m0 + g + 8) * WA + kb + 4];
                uint32_t al0 = KTlo[(m0 + g) * WA + kb];
                uint32_t al1 = KTlo[(m0 + g + 8) * WA + kb];
                uint32_t al2 = KTlo[(m0 + g) * WA + kb + 4];
                uint32_t al3 = KTlo[(m0 + g + 8) * WA + kb + 4];
#pragma unroll
                for (int nt = 0; nt < 4; nt++) {
                    const int nr = (n0 + nt * 8 + g) * WA + kb;
                    uint32_t bh0 = QThi[nr], bh1 = QThi[nr + 4];
                    uint32_t bl0 = QTlo[nr], bl1 = QTlo[nr + 4];
                    mma16816(acc[nt], ah0, ah1, ah2, ah3, bh0, bh1);
                    mma16816(acc[nt], ah0, ah1, ah2, ah3, bl0, bl1);
                    mma16816(acc[nt], al0, al1, al2, al3, bh0, bh1);
                }
            }
        }

        // Epilogue: C[m=d1][n=d2] -> P[d2][d1]  (P = M^T partial for this chunk)
        float* Pb = M_part + (size_t)blk * 4096;
#pragma unroll
        for (int nt = 0; nt < 4; nt++) {
            int d2 = n0 + nt * 8 + tg * 2;
            int d1 = m0 + g;
            Pb[d2 * 64 + d1]           = acc[nt][0];
            Pb[(d2 + 1) * 64 + d1]     = acc[nt][1];
            Pb[d2 * 64 + d1 + 8]       = acc[nt][2];
            Pb[(d2 + 1) * 64 + d1 + 8] = acc[nt][3];
        }
    }

    grid_barrier();     // all partials visible

    // ========================== Phase C ====================================
    {
        // Stage MT[d][dp] = sum_chunks P[d][dp], split hi/lo. 64 rows x 32 words.
        const float* Pb8 = M_part + (size_t)(b * 8) * 4096;
        {
            const int d = warp * 8 + dd;
#pragma unroll
            for (int j = 0; j < 8; j++) {
                int w = wq + 4 * j;                  // word 0..31, dp = 2w
                float s0 = 0.0f, s1 = 0.0f;
#pragma unroll
                for (int chk = 0; chk < 8; chk++) {
                    float2 v = *(const float2*)(Pb8 + (size_t)chk * 4096 + d * 64 + 2 * w);
                    s0 += v.x; s1 += v.y;
                }
                uint32_t hi, lo;
                split2(s0, s1, hi, lo);
                MThi[d * WA + w] = hi;  MTlo[d * WA + w] = lo;
            }
        }

        const float* Vc = V + ((size_t)b * SEQ + (size_t)c * 256) * DIM;

        for (int vt = 0; vt < 2; vt++) {
            float acc2[8][4];
#pragma unroll
            for (int nt = 0; nt < 8; nt++)
#pragma unroll
                for (int i = 0; i < 4; i++) acc2[nt][i] = 0.0f;

            for (int pass = 0; pass < 2; pass++) {
                __syncthreads();         // previous Vsh users done (also orders MT stage)
                // Stage V tile [128 rows][16 words], rows vt*128.., dp = pass*32..
#pragma unroll
                for (int j = 0; j < 8; j++) {
                    int v = warp * 16 + dd + 8 * (j & 1);
                    int w = wq + 4 * (j >> 1);       // 0..15
                    int dp = pass * 32 + 2 * w;
                    float2 vv = *(const float2*)(Vc + (size_t)(vt * 128 + v) * DIM + dp);
                    uint32_t hi, lo;
                    split2(vv.x, vv.y, hi, lo);
                    Vhi[v * WV + w] = hi;  Vlo[v * WV + w] = lo;
                }
                __syncthreads();

#pragma unroll
                for (int ks = 0; ks < 2; ks++) {
                    const int kv = ks * 8 + tg;              // within V tile
                    const int km = pass * 16 + ks * 8 + tg;  // within MT
                    const int mrow = warp * 16 + g;
                    uint32_t ah0 = Vhi[mrow * WV + kv];
                    uint32_t ah1 = Vhi[(mrow + 8) * WV + kv];
                    uint32_t ah2 = Vhi[mrow * WV + kv + 4];
                    uint32_t ah3 = Vhi[(mrow + 8) * WV + kv + 4];
                    uint32_t al0 = Vlo[mrow * WV + kv];
                    uint32_t al1 = Vlo[(mrow + 8) * WV + kv];
                    uint32_t al2 = Vlo[mrow * WV + kv + 4];
                    uint32_t al3 = Vlo[(mrow + 8) * WV + kv + 4];
#pragma unroll
                    for (int nt = 0; nt < 8; nt++) {
                        const int nr = (nt * 8 + g) * WA + km;
                        uint32_t bh0 = MThi[nr], bh1 = MThi[nr + 4];
                        uint32_t bl0 = MTlo[nr], bl1 = MTlo[nr + 4];
                        mma16816(acc2[nt], ah0, ah1, ah2, ah3, bh0, bh1);
                        mma16816(acc2[nt], ah0, ah1, ah2, ah3, bl0, bl1);
                        mma16816(acc2[nt], al0, al1, al2, al3, bh0, bh1);
                    }
                }
            }

            // Write O for this v-tile: C[v][d], rows warp*16+g (+8), cols nt*8+tg*2
            float* Ob = O + ((size_t)b * SEQ + (size_t)c * 256 + vt * 128 + warp * 16) * DIM;
#pragma unroll
            for (int nt = 0; nt < 8; nt++) {
                int col = nt * 8 + tg * 2;
                *(float2*)(Ob + (size_t)g * DIM + col) =
                    make_float2(acc2[nt][0], acc2[nt][1]);
                *(float2*)(Ob + (size_t)(g + 8) * DIM + col) =
                    make_float2(acc2[nt][2], acc2[nt][3]);
            }
        }
    }
}

// ---------------------------------------------------------------------------
extern "C" void kernel_launch(void* const* d_in, const int* in_sizes, int n_in,
                              void* d_out, int out_size) {
    const float* Q = (const float*)d_in[0];
    const float* K = (const float*)d_in[1];
    const float* V = (const float*)d_in[2];
    float* O = (float*)d_out;

    fused_attn_hmma<<<NBLK, NT>>>(Q, K, V, O);
}

// round 11
// speedup vs baseline: 1.3824x; 1.1218x over previous
#include <cuda_runtime.h>
#include <cuda_bf16.h>
#include <cstdint>

#define SEQ  2048
#define DIM  64
#define NBLK 128          // 16 batches x 8 seq-chunks; one wave on 148 SMs
#define NT   256

// P[d2][d1] = M[d1][d2] partials per (batch,chunk): 64x64 fp32. 2MB, L2-resident.
__device__ float M_part[NBLK * DIM * DIM];
__device__ unsigned bar_cnt = 0;
__device__ volatile unsigned bar_gen = 0;

// smem tile byte offsets (36KB total). Row stride 144B = 64 bf16 + 16B pad
// (multiple of 16B for ldmatrix; 36-word stride -> conflict-free 4i bank walk).
#define T_HI0   0        // Khi   | MThi
#define T_LO0   9216     // Klo   | MTlo
#define T_HI1   18432    // Qhi   | Vhi
#define T_LO1   27648    // Qlo   | Vlo
#define TROW    144

__device__ __forceinline__ uint32_t smem_u32(const void* p){
    uint32_t a;
    asm("{ .reg .u64 t; cvta.to.shared.u64 t, %1; cvt.u32.u64 %0, t; }" : "=r"(a) : "l"(p));
    return a;
}
__device__ __forceinline__ uint32_t bf16x2_of(float fo, float fe){
    uint32_t r;
    asm("cvt.rn.bf16x2.f32 %0, %1, %2;" : "=r"(r) : "f"(fo), "f"(fe));
    return r;
}
// split fp32 (fe=even idx, fo=odd idx) -> hi word {bf16(fo),bf16(fe)} + residual word
__device__ __forceinline__ void cvt_pair(float fe, float fo, uint32_t &hi, uint32_t &lo){
    hi = bf16x2_of(fo, fe);
    float he = __uint_as_float(hi << 16);
    float ho = __uint_as_float(hi & 0xffff0000u);
    lo = bf16x2_of(fo - ho, fe - he);
}
__device__ __forceinline__ void mma16816(float* c, const uint32_t* a,
                                         uint32_t b0, uint32_t b1){
    asm("mma.sync.aligned.m16n8k16.row.col.f32.bf16.bf16.f32 "
        "{%0,%1,%2,%3}, {%4,%5,%6,%7}, {%8,%9}, {%0,%1,%2,%3};"
        : "+f"(c[0]), "+f"(c[1]), "+f"(c[2]), "+f"(c[3])
        : "r"(a[0]), "r"(a[1]), "r"(a[2]), "r"(a[3]), "r"(b0), "r"(b1));
}
__device__ __forceinline__ void ldsm4(uint32_t* r, uint32_t addr){
    asm volatile("ldmatrix.sync.aligned.m8n8.x4.shared.b16 {%0,%1,%2,%3}, [%4];"
        : "=r"(r[0]), "=r"(r[1]), "=r"(r[2]), "=r"(r[3]) : "r"(addr));
}
__device__ __forceinline__ void ldsm4t(uint32_t* r, uint32_t addr){
    asm volatile("ldmatrix.sync.aligned.m8n8.x4.trans.shared.b16 {%0,%1,%2,%3}, [%4];"
        : "=r"(r[0]), "=r"(r[1]), "=r"(r[2]), "=r"(r[3]) : "r"(addr));
}
__device__ __forceinline__ void grid_barrier(){
    __threadfence();
    __syncthreads();
    if (threadIdx.x == 0) {
        unsigned gen = bar_gen;
        unsigned arrived = atomicAdd(&bar_cnt, 1);
        if (arrived == gridDim.x - 1) {
            bar_cnt = 0;
            __threadfence();
            bar_gen = gen + 1;
        } else {
            while (bar_gen == gen) { }
        }
    }
    __syncthreads();
    __threadfence();
}

// Stage 16 fp32 (one row-chunk) as bf16 hi+lo into natural-layout tiles.
__device__ __forceinline__ void stage_tile(unsigned char* hiB, unsigned char* loB,
                                           const float4* f, int row, int chunk){
    uint32_t h[8], L[8];
#pragma unroll
    for (int j = 0; j < 4; j++){
        cvt_pair(f[j].x, f[j].y, h[2*j],   L[2*j]);
        cvt_pair(f[j].z, f[j].w, h[2*j+1], L[2*j+1]);
    }
    uint4* dh = (uint4*)(hiB + row * TROW + chunk * 32);
    dh[0] = make_uint4(h[0], h[1], h[2], h[3]);
    dh[1] = make_uint4(h[4], h[5], h[6], h[7]);
    uint4* dl = (uint4*)(loB + row * TROW + chunk * 32);
    dl[0] = make_uint4(L[0], L[1], L[2], L[3]);
    dl[1] = make_uint4(L[4], L[5], L[6], L[7]);
}

// ---------------------------------------------------------------------------
__global__ __launch_bounds__(NT, 1)
void fused_attn_hmma2(const float* __restrict__ Q, const float* __restrict__ K,
                      const float* __restrict__ V, float* __restrict__ O)
{
    __shared__ __align__(16) unsigned char sm[36864];
    const uint32_t sb = smem_u32(sm);

    const int t = threadIdx.x, warp = t >> 5, lane = t & 31;
    const int g = lane >> 2, tg = lane & 3;         // mma C/epilogue ids
    const int grp = lane >> 3, li = lane & 7;       // ldmatrix ids
    const int half8 = (grp & 1) << 3;
    const int krow  = ((grp >> 1) << 3) + li;       // trans-ldmatrix stored row
    const int wm = warp & 3, wn = warp >> 2;        // warp tile m0=16wm, n0=32wn
    const int m0 = wm * 16, n0 = wn * 32;
    const int blk = blockIdx.x, b = blk >> 3, c = blk & 7;

    const float* Kc = K + ((size_t)b * SEQ + (size_t)c * 256) * DIM;
    const float* Qc = Q + ((size_t)b * SEQ + (size_t)c * 256) * DIM;
    const float* Vc = V + ((size_t)b * SEQ + (size_t)c * 256) * DIM;

    const int srow = t >> 2, schunk = t & 3;        // staging coords

    // ========================== Phase A ====================================
    {
        float4 fK[4], fQ[4];
        {
            const float4* pk = (const float4*)(Kc + (size_t)srow * DIM + schunk * 16);
            const float4* pq = (const float4*)(Qc + (size_t)srow * DIM + schunk * 16);
#pragma unroll
            for (int j = 0; j < 4; j++){ fK[j] = pk[j]; fQ[j] = pq[j]; }
        }

        float acc[4][4];
#pragma unroll
        for (int q = 0; q < 4; q++)
#pragma unroll
            for (int i = 0; i < 4; i++) acc[q][i] = 0.0f;

        // trans-ldmatrix bases (K^T rows m, Q^T rows n; stored [s][d])
        const uint32_t aB  = sb + T_HI0 + krow * TROW + 2 * (m0 + half8);
        const uint32_t bB0 = sb + T_HI1 + krow * TROW + 2 * (n0 + half8);
        const uint32_t bB1 = bB0 + 32;      // +16 cols

        for (int sub = 0; sub < 4; sub++) {
            __syncthreads();                 // tile consumers of prev sub done
            stage_tile(sm + T_HI0, sm + T_LO0, fK, srow, schunk);
            stage_tile(sm + T_HI1, sm + T_LO1, fQ, srow, schunk);
            if (sub < 3) {                   // prefetch next sub (hides LDG)
                const float4* pk = (const float4*)(Kc + (size_t)((sub+1)*64 + srow) * DIM + schunk * 16);
                const float4* pq = (const float4*)(Qc + (size_t)((sub+1)*64 + srow) * DIM + schunk * 16);
#pragma unroll
                for (int j = 0; j < 4; j++){ fK[j] = pk[j]; fQ[j] = pq[j]; }
            }
            __syncthreads();

#pragma unroll
            for (int ks = 0; ks < 4; ks++) {
                uint32_t ah[4], al[4], bh[4], bl[4];
                ldsm4t(ah, aB + ks * 2304);
                ldsm4t(al, aB + ks * 2304 + 9216);
                ldsm4t(bh, bB0 + ks * 2304);
                ldsm4t(bl, bB0 + ks * 2304 + 9216);
                mma16816(acc[0], ah, bh[0], bh[2]);
                mma16816(acc[0], ah, bl[0], bl[2]);
                mma16816(acc[0], al, bh[0], bh[2]);
                mma16816(acc[1], ah, bh[1], bh[3]);
                mma16816(acc[1], ah, bl[1], bl[3]);
                mma16816(acc[1], al, bh[1], bh[3]);
                ldsm4t(bh, bB1 + ks * 2304);
                ldsm4t(bl, bB1 + ks * 2304 + 9216);
                mma16816(acc[2], ah, bh[0], bh[2]);
                mma16816(acc[2], ah, bl[0], bl[2]);
                mma16816(acc[2], al, bh[0], bh[2]);
                mma16816(acc[3], ah, bh[1], bh[3]);
                mma16816(acc[3], ah, bl[1], bl[3]);
                mma16816(acc[3], al, bh[1], bh[3]);
            }
        }

        // Epilogue: C[m=d1][n=d2] -> P[d2][d1] partial
        float* Pb = M_part + (size_t)blk * 4096;
#pragma unroll
        for (int q = 0; q < 4; q++) {
            int d2 = n0 + q * 8 + tg * 2;
            int d1 = m0 + g;
            Pb[d2 * 64 + d1]           = acc[q][0];
            Pb[(d2 + 1) * 64 + d1]     = acc[q][1];
            Pb[d2 * 64 + d1 + 8]       = acc[q][2];
            Pb[(d2 + 1) * 64 + d1 + 8] = acc[q][3];
        }
    }

    // Prefetch V vt0 before the barrier (V independent of M_part)
    float4 fV[4];
    {
        const float4* pv = (const float4*)(Vc + (size_t)srow * DIM + schunk * 16);
#pragma unroll
        for (int j = 0; j < 4; j++) fV[j] = pv[j];
    }

    grid_barrier();     // all partials visible

    // ========================== Phase C ====================================
    {
        // MT[d][dp] = sum_chunks P[d][dp], split hi/lo into natural tiles.
        {
            const int d = t >> 2, wq = t & 3;
            const float* base = M_part + (size_t)(b * 8) * 4096 + d * 64 + wq * 16;
#pragma unroll
            for (int j = 0; j < 8; j++) {
                float s0 = 0.0f, s1 = 0.0f;
#pragma unroll
                for (int chk = 0; chk < 8; chk++) {
                    float2 v = *(const float2*)(base + (size_t)chk * 4096 + 2 * j);
                    s0 += v.x; s1 += v.y;
                }
                uint32_t hi, lo;
                cvt_pair(s0, s1, hi, lo);
                *(uint32_t*)(sm + T_HI0 + d * TROW + (wq * 8 + j) * 4) = hi;
                *(uint32_t*)(sm + T_LO0 + d * TROW + (wq * 8 + j) * 4) = lo;
            }
        }
        // Stage V vt0, prefetch vt1
        stage_tile(sm + T_HI1, sm + T_LO1, fV, srow, schunk);
        {
            const float4* pv = (const float4*)(Vc + (size_t)(64 + srow) * DIM + schunk * 16);
#pragma unroll
            for (int j = 0; j < 4; j++) fV[j] = pv[j];
        }
        __syncthreads();

        // non-trans ldmatrix bases: A = V rows m, B = MT rows n; k along rows
        const uint32_t vB  = sb + T_HI1 + (m0 + half8 + li) * TROW + ((grp >> 1) << 4);
        const uint32_t mB0 = sb + T_HI0 + (n0 + half8 + li) * TROW + ((grp >> 1) << 4);
        const uint32_t mB1 = mB0 + 16 * TROW;

        for (int vt = 0; vt < 4; vt++) {
            float acc2[4][4];
#pragma unroll
            for (int q = 0; q < 4; q++)
#pragma unroll
                for (int i = 0; i < 4; i++) acc2[q][i] = 0.0f;

#pragma unroll
            for (int ks = 0; ks < 4; ks++) {
                uint32_t ah[4], al[4], bh[4], bl[4];
                ldsm4(ah, vB + ks * 32);
                ldsm4(al, vB + ks * 32 + 9216);
                ldsm4(bh, mB0 + ks * 32);
                ldsm4(bl, mB0 + ks * 32 + 9216);
                mma16816(acc2[0], ah, bh[0], bh[2]);
                mma16816(acc2[0], ah, bl[0], bl[2]);
                mma16816(acc2[0], al, bh[0], bh[2]);
                mma16816(acc2[1], ah, bh[1], bh[3]);
                mma16816(acc2[1], ah, bl[1], bl[3]);
                mma16816(acc2[1], al, bh[1], bh[3]);
                ldsm4(bh, mB1 + ks * 32);
                ldsm4(bl, mB1 + ks * 32 + 9216);
                mma16816(acc2[2], ah, bh[0], bh[2]);
                mma16816(acc2[2], ah, bl[0], bl[2]);
                mma16816(acc2[2], al, bh[0], bh[2]);
                mma16816(acc2[3], ah, bh[1], bh[3]);
                mma16816(acc2[3], ah, bl[1], bl[3]);
                mma16816(acc2[3], al, bh[1], bh[3]);
            }

            // Write O rows vt*64 + m0 + g (+8), cols n0 + q*8 + 2tg
            float* Ob = O + ((size_t)b * SEQ + (size_t)c * 256 + vt * 64 + m0) * DIM;
#pragma unroll
            for (int q = 0; q < 4; q++) {
                int col = n0 + q * 8 + tg * 2;
                *(float2*)(Ob + (size_t)g * DIM + col) =
                    make_float2(acc2[q][0], acc2[q][1]);
                *(float2*)(Ob + (size_t)(g + 8) * DIM + col) =
                    make_float2(acc2[q][2], acc2[q][3]);
            }

            if (vt < 3) {
                __syncthreads();             // frag reads of this vt done
                stage_tile(sm + T_HI1, sm + T_LO1, fV, srow, schunk);
                if (vt < 2) {
                    const float4* pv = (const float4*)(Vc + (size_t)((vt+2)*64 + srow) * DIM + schunk * 16);
#pragma unroll
                    for (int j = 0; j < 4; j++) fV[j] = pv[j];
                }
                __syncthreads();
            }
        }
    }
}

// ---------------------------------------------------------------------------
extern "C" void kernel_launch(void* const* d_in, const int* in_sizes, int n_in,
                              void* d_out, int out_size) {
    const float* Q = (const float*)d_in[0];
    const float* K = (const float*)d_in[1];
    const float* V = (const float*)d_in[2];
    float* O = (float*)d_out;

    fused_attn_hmma2<<<NBLK, NT>>>(Q, K, V, O);
}

// round 13
// speedup vs baseline: 1.4145x; 1.0232x over previous
#include <cuda_runtime.h>
#include <cuda_bf16.h>
#include <cstdint>

#define SEQ  2048
#define DIM  64
#define NBLK 256          // 16 batches x 16 s-chunks of 128 rows; 2 CTAs/SM
#define NT   256

// P[d2][d1] = M[d1][d2] partials per (batch,chunk): 64x64 fp32. 4MB, L2-resident.
__device__ float M_part[NBLK * DIM * DIM];
// Reduced M per batch (P layout [d][dp]): 16 x 4096 fp32 = 256KB.
__device__ float M_final[16 * DIM * DIM];
__device__ unsigned bar_cnt = 0;
__device__ volatile unsigned bar_gen = 0;

// smem tile byte offsets (36KB/CTA). Row stride 144B = 64 bf16 + 16B pad
// (16B-multiple for ldmatrix; 36-word stride -> conflict-free bank walk).
#define T_HI0   0        // Khi   | MThi
#define T_LO0   9216     // Klo   | MTlo
#define T_HI1   18432    // Qhi   | Vhi
#define T_LO1   27648    // Qlo   | Vlo
#define TROW    144

__device__ __forceinline__ uint32_t smem_u32(const void* p){
    uint32_t a;
    asm("{ .reg .u64 t; cvta.to.shared.u64 t, %1; cvt.u32.u64 %0, t; }" : "=r"(a) : "l"(p));
    return a;
}
__device__ __forceinline__ uint32_t bf16x2_of(float fo, float fe){
    uint32_t r;
    asm("cvt.rn.bf16x2.f32 %0, %1, %2;" : "=r"(r) : "f"(fo), "f"(fe));
    return r;
}
// split fp32 (fe=even idx, fo=odd idx) -> hi word {bf16(fo),bf16(fe)} + residual word
__device__ __forceinline__ void cvt_pair(float fe, float fo, uint32_t &hi, uint32_t &lo){
    hi = bf16x2_of(fo, fe);
    float he = __uint_as_float(hi << 16);
    float ho = __uint_as_float(hi & 0xffff0000u);
    lo = bf16x2_of(fo - ho, fe - he);
}
__device__ __forceinline__ void mma16816(float* c, const uint32_t* a,
                                         uint32_t b0, uint32_t b1){
    asm("mma.sync.aligned.m16n8k16.row.col.f32.bf16.bf16.f32 "
        "{%0,%1,%2,%3}, {%4,%5,%6,%7}, {%8,%9}, {%0,%1,%2,%3};"
        : "+f"(c[0]), "+f"(c[1]), "+f"(c[2]), "+f"(c[3])
        : "r"(a[0]), "r"(a[1]), "r"(a[2]), "r"(a[3]), "r"(b0), "r"(b1));
}
__device__ __forceinline__ void ldsm4(uint32_t* r, uint32_t addr){
    asm volatile("ldmatrix.sync.aligned.m8n8.x4.shared.b16 {%0,%1,%2,%3}, [%4];"
        : "=r"(r[0]), "=r"(r[1]), "=r"(r[2]), "=r"(r[3]) : "r"(addr));
}
__device__ __forceinline__ void ldsm4t(uint32_t* r, uint32_t addr){
    asm volatile("ldmatrix.sync.aligned.m8n8.x4.trans.shared.b16 {%0,%1,%2,%3}, [%4];"
        : "=r"(r[0]), "=r"(r[1]), "=r"(r[2]), "=r"(r[3]) : "r"(addr));
}
__device__ __forceinline__ void grid_barrier(){
    __threadfence();
    __syncthreads();
    if (threadIdx.x == 0) {
        unsigned gen = bar_gen;
        unsigned arrived = atomicAdd(&bar_cnt, 1);
        if (arrived == gridDim.x - 1) {
            bar_cnt = 0;
            __threadfence();
            bar_gen = gen + 1;
        } else {
            while (bar_gen == gen) { }
        }
    }
    __syncthreads();
    __threadfence();
}

// Stage 16 fp32 (one row-chunk) as bf16 hi+lo into natural-layout tiles.
__device__ __forceinline__ void stage_tile(unsigned char* hiB, unsigned char* loB,
                                           const float4* f, int row, int chunk){
    uint32_t h[8], L[8];
#pragma unroll
    for (int j = 0; j < 4; j++){
        cvt_pair(f[j].x, f[j].y, h[2*j],   L[2*j]);
        cvt_pair(f[j].z, f[j].w, h[2*j+1], L[2*j+1]);
    }
    uint4* dh = (uint4*)(hiB + row * TROW + chunk * 32);
    dh[0] = make_uint4(h[0], h[1], h[2], h[3]);
    dh[1] = make_uint4(h[4], h[5], h[6], h[7]);
    uint4* dl = (uint4*)(loB + row * TROW + chunk * 32);
    dl[0] = make_uint4(L[0], L[1], L[2], L[3]);
    dl[1] = make_uint4(L[4], L[5], L[6], L[7]);
}

// ---------------------------------------------------------------------------
// 256 blocks x 256 threads, 2 CTAs/SM (cross-CTA overlap hides stage latency).
// Phase A: partial K^T Q over this block's 128 s-rows (2 subs of 64).
// barrier -> Phase R: 16 partials reduced into M_final (each block: 256 words)
// barrier -> Phase C: O rows = V @ M via M_final, 2 v-tiles of 64 rows.
// ---------------------------------------------------------------------------
__global__ __launch_bounds__(NT, 2)
void fused_attn_hmma3(const float* __restrict__ Q, const float* __restrict__ K,
                      const float* __restrict__ V, float* __restrict__ O)
{
    __shared__ __align__(16) unsigned char sm[36864];
    const uint32_t sb = smem_u32(sm);

    const int t = threadIdx.x, warp = t >> 5, lane = t & 31;
    const int g = lane >> 2, tg = lane & 3;         // mma C/epilogue ids
    const int grp = lane >> 3, li = lane & 7;       // ldmatrix ids
    const int half8 = (grp & 1) << 3;
    const int krow  = ((grp >> 1) << 3) + li;       // trans-ldmatrix stored row
    const int wm = warp & 3, wn = warp >> 2;        // warp tile m0=16wm, n0=32wn
    const int m0 = wm * 16, n0 = wn * 32;
    const int blk = blockIdx.x, b = blk >> 4, c = blk & 15;

    const float* Kc = K + ((size_t)b * SEQ + (size_t)c * 128) * DIM;
    const float* Qc = Q + ((size_t)b * SEQ + (size_t)c * 128) * DIM;
    const float* Vc = V + ((size_t)b * SEQ + (size_t)c * 128) * DIM;

    const int srow = t >> 2, schunk = t & 3;        // staging coords (64 rows x 4 chunks)

    // ========================== Phase A ====================================
    {
        float acc[4][4];
#pragma unroll
        for (int q = 0; q < 4; q++)
#pragma unroll
            for (int i = 0; i < 4; i++) acc[q][i] = 0.0f;

        // trans-ldmatrix bases (K^T rows m, Q^T rows n; tiles stored [s][d])
        const uint32_t aB  = sb + T_HI0 + krow * TROW + 2 * (m0 + half8);
        const uint32_t bB0 = sb + T_HI1 + krow * TROW + 2 * (n0 + half8);
        const uint32_t bB1 = bB0 + 32;      // +16 cols

        for (int sub = 0; sub < 2; sub++) {
            __syncthreads();                 // tile consumers of prev sub done
            {
                const float4* pk = (const float4*)(Kc + (size_t)(sub * 64 + srow) * DIM + schunk * 16);
                const float4* pq = (const float4*)(Qc + (size_t)(sub * 64 + srow) * DIM + schunk * 16);
                float4 fK[4], fQ[4];
#pragma unroll
                for (int j = 0; j < 4; j++){ fK[j] = pk[j]; fQ[j] = pq[j]; }
                stage_tile(sm + T_HI0, sm + T_LO0, fK, srow, schunk);
                stage_tile(sm + T_HI1, sm + T_LO1, fQ, srow, schunk);
            }
            __syncthreads();

#pragma unroll
            for (int ks = 0; ks < 4; ks++) {
                uint32_t ah[4], al[4], bh[4], bl[4];
                ldsm4t(ah, aB + ks * 2304);
                ldsm4t(al, aB + ks * 2304 + 9216);
                ldsm4t(bh, bB0 + ks * 2304);
                ldsm4t(bl, bB0 + ks * 2304 + 9216);
                mma16816(acc[0], ah, bh[0], bh[2]);
                mma16816(acc[0], ah, bl[0], bl[2]);
                mma16816(acc[0], al, bh[0], bh[2]);
                mma16816(acc[1], ah, bh[1], bh[3]);
                mma16816(acc[1], ah, bl[1], bl[3]);
                mma16816(acc[1], al, bh[1], bh[3]);
                ldsm4t(bh, bB1 + ks * 2304);
                ldsm4t(bl, bB1 + ks * 2304 + 9216);
                mma16816(acc[2], ah, bh[0], bh[2]);
                mma16816(acc[2], ah, bl[0], bl[2]);
                mma16816(acc[2], al, bh[0], bh[2]);
                mma16816(acc[3], ah, bh[1], bh[3]);
                mma16816(acc[3], ah, bl[1], bl[3]);
                mma16816(acc[3], al, bh[1], bh[3]);
            }
        }

        // Epilogue: C[m=d1][n=d2] -> P[d2][d1] partial
        float* Pb = M_part + (size_t)blk * 4096;
#pragma unroll
        for (int q = 0; q < 4; q++) {
            int d2 = n0 + q * 8 + tg * 2;
            int d1 = m0 + g;
            Pb[d2 * 64 + d1]           = acc[q][0];
            Pb[(d2 + 1) * 64 + d1]     = acc[q][1];
            Pb[d2 * 64 + d1 + 8]       = acc[q][2];
            Pb[(d2 + 1) * 64 + d1 + 8] = acc[q][3];
        }
    }

    grid_barrier();     // all partials visible

    // ============ Phase R: reduce 16 chunk partials -> M_final =============
    {
        const float* src = M_part + (size_t)(b * 16) * 4096 + c * 256 + t;
        float s = 0.0f;
#pragma unroll
        for (int chk = 0; chk < 16; chk++) s += src[(size_t)chk * 4096];
        M_final[b * 4096 + c * 256 + t] = s;
    }

    grid_barrier();     // M_final visible

    // ========================== Phase C ====================================
    {
        // Stage MT[d][dp] = M_final (P layout [d][dp]), split hi/lo.
        {
            const int d = t >> 2, wq = t & 3;
            const float* base = M_final + b * 4096 + d * 64 + wq * 16;
#pragma unroll
            for (int j = 0; j < 8; j++) {
                float2 v = *(const float2*)(base + 2 * j);
                uint32_t hi, lo;
                cvt_pair(v.x, v.y, hi, lo);
                *(uint32_t*)(sm + T_HI0 + d * TROW + (wq * 8 + j) * 4) = hi;
                *(uint32_t*)(sm + T_LO0 + d * TROW + (wq * 8 + j) * 4) = lo;
            }
        }
        // Stage V vt0
        {
            const float4* pv = (const float4*)(Vc + (size_t)srow * DIM + schunk * 16);
            float4 fV[4];
#pragma unroll
            for (int j = 0; j < 4; j++) fV[j] = pv[j];
            stage_tile(sm + T_HI1, sm + T_LO1, fV, srow, schunk);
        }
        __syncthreads();

        // non-trans ldmatrix bases: A = V rows m, B = MT rows n; k along rows
        const uint32_t vB  = sb + T_HI1 + (m0 + half8 + li) * TROW + ((grp >> 1) << 4);
        const uint32_t mB0 = sb + T_HI0 + (n0 + half8 + li) * TROW + ((grp >> 1) << 4);
        const uint32_t mB1 = mB0 + 16 * TROW;

        for (int vt = 0; vt < 2; vt++) {
            float acc2[4][4];
#pragma unroll
            for (int q = 0; q < 4; q++)
#pragma unroll
                for (int i = 0; i < 4; i++) acc2[q][i] = 0.0f;

#pragma unroll
            for (int ks = 0; ks < 4; ks++) {
                uint32_t ah[4], al[4], bh[4], bl[4];
                ldsm4(ah, vB + ks * 32);
                ldsm4(al, vB + ks * 32 + 9216);
                ldsm4(bh, mB0 + ks * 32);
                ldsm4(bl, mB0 + ks * 32 + 9216);
                mma16816(acc2[0], ah, bh[0], bh[2]);
                mma16816(acc2[0], ah, bl[0], bl[2]);
                mma16816(acc2[0], al, bh[0], bh[2]);
                mma16816(acc2[1], ah, bh[1], bh[3]);
                mma16816(acc2[1], ah, bl[1], bl[3]);
                mma16816(acc2[1], al, bh[1], bh[3]);
                ldsm4(bh, mB1 + ks * 32);
                ldsm4(bl, mB1 + ks * 32 + 9216);
                mma16816(acc2[2], ah, bh[0], bh[2]);
                mma16816(acc2[2], ah, bl[0], bl[2]);
                mma16816(acc2[2], al, bh[0], bh[2]);
                mma16816(acc2[3], ah, bh[1], bh[3]);
                mma16816(acc2[3], ah, bl[1], bl[3]);
                mma16816(acc2[3], al, bh[1], bh[3]);
            }

            // Write O rows c*128 + vt*64 + m0 + g (+8), cols n0 + q*8 + 2tg
            float* Ob = O + ((size_t)b * SEQ + (size_t)c * 128 + vt * 64 + m0) * DIM;
#pragma unroll
            for (int q = 0; q < 4; q++) {
                int col = n0 + q * 8 + tg * 2;
                *(float2*)(Ob + (size_t)g * DIM + col) =
                    make_float2(acc2[q][0], acc2[q][1]);
                *(float2*)(Ob + (size_t)(g + 8) * DIM + col) =
                    make_float2(acc2[q][2], acc2[q][3]);
            }

            if (vt == 0) {
                __syncthreads();             // frag reads of vt0 done
                const float4* pv = (const float4*)(Vc + (size_t)(64 + srow) * DIM + schunk * 16);
                float4 fV[4];
#pragma unroll
                for (int j = 0; j < 4; j++) fV[j] = pv[j];
                stage_tile(sm + T_HI1, sm + T_LO1, fV, srow, schunk);
                __syncthreads();
            }
        }
    }
}

// ---------------------------------------------------------------------------
extern "C" void kernel_launch(void* const* d_in, const int* in_sizes, int n_in,
                              void* d_out, int out_size) {
    const float* Q = (const float*)d_in[0];
    const float* K = (const float*)d_in[1];
    const float* V = (const float*)d_in[2];
    float* O = (float*)d_out;

    fused_attn_hmma3<<<NBLK, NT>>>(Q, K, V, O);
}